// round 7
// baseline (speedup 1.0000x reference)
#include <cuda_runtime.h>
#include <cstdint>

// dense_image_warp: out[b,y,x,c] = bilinear(image[b], y - flow[b,y,x,0], x - flow[b,y,x,1])
// B=8, H=512, W=512, C=16, fp32.
//
// Block = 256 threads = 16(w) x 4(h) pixels x 4 channel groups, iterated 4x to
// cover a 16x16 output tile. The block stages a 24x24-pixel image tile
// (16x16 + 4px halo, 36.8KB) into smem with coalesced cp.async, then all
// bilinear gathers are LDS. Samples falling outside the halo (|flow|>~4,
// prob ~6e-5) take a correct global-load fallback.

#define Hh 512
#define Ww 512
#define TP 24                 // tile pixels per side (16 + 2*4 halo)
#define TILE_F4 (TP*TP*4)     // 2304 float4 = 36864 B

__global__ __launch_bounds__(256) void warp_tile_smem(
    const float4* __restrict__ img4,   // image as float4 (4 channels per group)
    const float2* __restrict__ flow2,  // flow as float2 per pixel
    float4* __restrict__ out4)
{
    __shared__ float4 stile[TILE_F4];

    int t  = threadIdx.x;
    int cg = t & 3;
    int lx = (t >> 2) & 15;
    int ly = t >> 6;                   // 0..3

    int x0 = blockIdx.x * 16;
    int y0 = blockIdx.y * 16;
    int b  = blockIdx.z;
    int x  = x0 + lx;

    // tile origin, clamped so the 24x24 window stays in-image
    int ys0 = y0 - 4; ys0 = ys0 < 0 ? 0 : (ys0 > Hh - TP ? Hh - TP : ys0);
    int xs0 = x0 - 4; xs0 = xs0 < 0 ? 0 : (xs0 > Ww - TP ? Ww - TP : xs0);

    // ---- issue flow loads for all 4 iterations (latency hides under tile load)
    float2 f[4];
    #pragma unroll
    for (int it = 0; it < 4; it++) {
        int y = y0 + it * 4 + ly;
        f[it] = __ldg(&flow2[(((b << 9) + y) << 9) + x]);
    }

    // ---- stage 24x24 image tile into smem via cp.async (9 x 16B per thread)
    {
        const char* gbase = (const char*)img4
            + ((size_t)(((b << 9) + ys0) << 9) + xs0) * 64;
        uint32_t sbase = (uint32_t)__cvta_generic_to_shared(stile);
        #pragma unroll
        for (int i = 0; i < 9; i++) {
            int idx = i * 256 + t;          // 0..2303 (16B chunks)
            int r   = idx / 96;             // 96 chunks (1536B) per pixel row
            int c   = idx - r * 96;
            const char* g = gbase + (size_t)r * (Ww * 64) + c * 16;
            uint32_t s = sbase + idx * 16;
            asm volatile("cp.async.cg.shared.global [%0], [%1], 16;\n"
                         :: "r"(s), "l"(g) : "memory");
        }
        asm volatile("cp.async.commit_group;\n" ::: "memory");
        asm volatile("cp.async.wait_group 0;\n" ::: "memory");
    }
    __syncthreads();

    #pragma unroll
    for (int it = 0; it < 4; it++) {
        int y = y0 + it * 4 + ly;

        float qy = (float)y - f[it].x;
        float qx = (float)x - f[it].y;

        float fy = fminf(fmaxf(floorf(qy), 0.0f), (float)(Hh - 2));
        float fx = fminf(fmaxf(floorf(qx), 0.0f), (float)(Ww - 2));
        float ay = fminf(fmaxf(qy - fy, 0.0f), 1.0f);
        float ax = fminf(fmaxf(qx - fx, 0.0f), 1.0f);
        int iy = (int)fy;
        int ix = (int)fx;

        int ry = iy - ys0;
        int rx = ix - xs0;

        float4 tl, tr, bl, br;
        if ((unsigned)ry <= (unsigned)(TP - 2) && (unsigned)rx <= (unsigned)(TP - 2)) {
            int s = (ry * TP + rx) * 4 + cg;
            tl = stile[s];
            tr = stile[s + 4];
            bl = stile[s + TP * 4];
            br = stile[s + TP * 4 + 4];
        } else {
            // rare fallback: sample outside staged halo
            int base = (((b << 9) + iy) << 9) + ix;
            int a_tl = (base << 2) + cg;
            int a_bl = a_tl + (Ww << 2);
            tl = __ldg(&img4[a_tl]);
            tr = __ldg(&img4[a_tl + 4]);
            bl = __ldg(&img4[a_bl]);
            br = __ldg(&img4[a_bl + 4]);
        }

        float4 top, bot, r;
        top.x = fmaf(ax, tr.x - tl.x, tl.x);
        top.y = fmaf(ax, tr.y - tl.y, tl.y);
        top.z = fmaf(ax, tr.z - tl.z, tl.z);
        top.w = fmaf(ax, tr.w - tl.w, tl.w);
        bot.x = fmaf(ax, br.x - bl.x, bl.x);
        bot.y = fmaf(ax, br.y - bl.y, bl.y);
        bot.z = fmaf(ax, br.z - bl.z, bl.z);
        bot.w = fmaf(ax, br.w - bl.w, bl.w);
        r.x = fmaf(ay, bot.x - top.x, top.x);
        r.y = fmaf(ay, bot.y - top.y, top.y);
        r.z = fmaf(ay, bot.z - top.z, top.z);
        r.w = fmaf(ay, bot.w - top.w, top.w);

        int p = (((b << 9) + y) << 9) + x;
        out4[(p << 2) + cg] = r;
    }
}

extern "C" void kernel_launch(void* const* d_in, const int* in_sizes, int n_in,
                              void* d_out, int out_size)
{
    const float4* img4  = (const float4*)d_in[0];
    const float2* flow2 = (const float2*)d_in[1];
    float4* out4 = (float4*)d_out;

    dim3 grid(Ww / 16, Hh / 16, 8);
    warp_tile_smem<<<grid, 256>>>(img4, flow2, out4);
}

// round 8
// speedup vs baseline: 1.1411x; 1.1411x over previous
#include <cuda_runtime.h>
#include <cstdint>

// dense_image_warp: out[b,y,x,c] = bilinear(image[b], y - flow[b,y,x,0], x - flow[b,y,x,1])
// B=8, H=512, W=512, C=16, fp32.
// Block = 256 threads = 16(w) x 4(h) pixels x 4 channel groups, 4 iterations
// covering a 16x16 output tile. Flow staged in smem (cp.async). Streaming
// cache hints (.cs) on the write-once output and read-once flow keep L2
// capacity for the image gather working set.

#define Hh 512
#define Ww 512

__global__ __launch_bounds__(256) void warp_kernel_cs(
    const float4* __restrict__ img4,   // image as float4 (4 channels per group)
    const float2* __restrict__ flow2,  // flow as float2 per pixel
    float4* __restrict__ out4)
{
    __shared__ float2 sflow[256];      // 16x16 pixel flow tile

    int t  = threadIdx.x;
    int cg = t & 3;                    // channel group
    int lx = (t >> 2) & 15;            // 0..15
    int ly = t >> 6;                   // 0..3

    int x  = blockIdx.x * 16 + lx;
    int y0 = blockIdx.y * 16;
    int b  = blockIdx.z;

    // ---- stage flow tile (read-once -> evict-first via __ldcs) ----
    {
        int fxp = blockIdx.x * 16 + (t & 15);
        int fyp = y0 + (t >> 4);
        int fp  = (((b << 9) + fyp) << 9) + fxp;
        sflow[t] = __ldcs(&flow2[fp]);
    }
    __syncthreads();

    #pragma unroll
    for (int it = 0; it < 4; it++) {
        int y = y0 + it * 4 + ly;

        float2 f = sflow[((it * 4 + ly) << 4) + lx];
        float qy = (float)y - f.x;
        float qx = (float)x - f.y;

        float fy = fminf(fmaxf(floorf(qy), 0.0f), (float)(Hh - 2));
        float fx = fminf(fmaxf(floorf(qx), 0.0f), (float)(Ww - 2));
        float ay = fminf(fmaxf(qy - fy, 0.0f), 1.0f);
        float ax = fminf(fmaxf(qx - fx, 0.0f), 1.0f);
        int iy = (int)fy;
        int ix = (int)fx;

        int base = (((b << 9) + iy) << 9) + ix;   // TL pixel index
        int a_tl = (base << 2) + cg;
        int a_bl = a_tl + (Ww << 2);

        float4 tl = __ldg(&img4[a_tl]);
        float4 tr = __ldg(&img4[a_tl + 4]);
        float4 bl = __ldg(&img4[a_bl]);
        float4 br = __ldg(&img4[a_bl + 4]);

        float4 top, bot, r;
        top.x = fmaf(ax, tr.x - tl.x, tl.x);
        top.y = fmaf(ax, tr.y - tl.y, tl.y);
        top.z = fmaf(ax, tr.z - tl.z, tl.z);
        top.w = fmaf(ax, tr.w - tl.w, tl.w);
        bot.x = fmaf(ax, br.x - bl.x, bl.x);
        bot.y = fmaf(ax, br.y - bl.y, bl.y);
        bot.z = fmaf(ax, br.z - bl.z, bl.z);
        bot.w = fmaf(ax, br.w - bl.w, bl.w);
        r.x = fmaf(ay, bot.x - top.x, top.x);
        r.y = fmaf(ay, bot.y - top.y, top.y);
        r.z = fmaf(ay, bot.z - top.z, top.z);
        r.w = fmaf(ay, bot.w - top.w, top.w);

        int p = (((b << 9) + y) << 9) + x;
        __stcs(&out4[(p << 2) + cg], r);   // write-once -> evict-first
    }
}

extern "C" void kernel_launch(void* const* d_in, const int* in_sizes, int n_in,
                              void* d_out, int out_size)
{
    const float4* img4  = (const float4*)d_in[0];
    const float2* flow2 = (const float2*)d_in[1];
    float4* out4 = (float4*)d_out;

    dim3 grid(Ww / 16, Hh / 16, 8);
    warp_kernel_cs<<<grid, 256>>>(img4, flow2, out4);
}

// round 9
// speedup vs baseline: 1.1591x; 1.0157x over previous
#include <cuda_runtime.h>
#include <cstdint>

// dense_image_warp: out[b,y,x,c] = bilinear(image[b], y - flow[b,y,x,0], x - flow[b,y,x,1])
// B=8, H=512, W=512, C=16, fp32.
// Block = 256 threads = 16(w) x 4(h) px x 4 channel groups, 4 iterations for a
// 16x16 output tile. Flow staged in smem. Results accumulated in a 16KB smem
// tile and written out as 16 x 1KB cp.async.bulk (shared->global) bursts,
// removing store wavefronts from L1tex and giving HBM full write bursts.

#define Hh 512
#define Ww 512

__global__ __launch_bounds__(256) void warp_kernel_bulk(
    const float4* __restrict__ img4,   // image as float4 (4 channels per group)
    const float2* __restrict__ flow2,  // flow as float2 per pixel
    float4* __restrict__ out4)
{
    __shared__ float2 sflow[256];        // 16x16 flow tile
    __shared__ alignas(128) float4 sout[16 * 64];  // 16 rows x 1KB = 16KB

    int t  = threadIdx.x;
    int cg = t & 3;                    // channel group
    int lx = (t >> 2) & 15;            // 0..15
    int ly = t >> 6;                   // 0..3

    int x0 = blockIdx.x * 16;
    int y0 = blockIdx.y * 16;
    int b  = blockIdx.z;
    int x  = x0 + lx;

    // ---- stage flow tile (read-once) ----
    {
        int fxp = x0 + (t & 15);
        int fyp = y0 + (t >> 4);
        int fp  = (((b << 9) + fyp) << 9) + fxp;
        sflow[t] = __ldcs(&flow2[fp]);
    }
    __syncthreads();

    #pragma unroll
    for (int it = 0; it < 4; it++) {
        int ty = it * 4 + ly;          // row within tile: 0..15
        int y  = y0 + ty;

        float2 f = sflow[(ty << 4) + lx];
        float qy = (float)y - f.x;
        float qx = (float)x - f.y;

        float fy = fminf(fmaxf(floorf(qy), 0.0f), (float)(Hh - 2));
        float fx = fminf(fmaxf(floorf(qx), 0.0f), (float)(Ww - 2));
        float ay = fminf(fmaxf(qy - fy, 0.0f), 1.0f);
        float ax = fminf(fmaxf(qx - fx, 0.0f), 1.0f);
        int iy = (int)fy;
        int ix = (int)fx;

        int base = (((b << 9) + iy) << 9) + ix;   // TL pixel index
        int a_tl = (base << 2) + cg;
        int a_bl = a_tl + (Ww << 2);

        float4 tl = __ldg(&img4[a_tl]);
        float4 tr = __ldg(&img4[a_tl + 4]);
        float4 bl = __ldg(&img4[a_bl]);
        float4 br = __ldg(&img4[a_bl + 4]);

        float4 top, bot, r;
        top.x = fmaf(ax, tr.x - tl.x, tl.x);
        top.y = fmaf(ax, tr.y - tl.y, tl.y);
        top.z = fmaf(ax, tr.z - tl.z, tl.z);
        top.w = fmaf(ax, tr.w - tl.w, tl.w);
        bot.x = fmaf(ax, br.x - bl.x, bl.x);
        bot.y = fmaf(ax, br.y - bl.y, bl.y);
        bot.z = fmaf(ax, br.z - bl.z, bl.z);
        bot.w = fmaf(ax, br.w - bl.w, bl.w);
        r.x = fmaf(ay, bot.x - top.x, top.x);
        r.y = fmaf(ay, bot.y - top.y, top.y);
        r.z = fmaf(ay, bot.z - top.z, top.z);
        r.w = fmaf(ay, bot.w - top.w, top.w);

        // accumulate in smem tile: row ty, 64 float4 per row, conflict-free
        sout[(ty << 6) + (lx << 2) + cg] = r;
    }

    __syncthreads();
    // make generic-proxy STS visible to the async proxy
    asm volatile("fence.proxy.async.shared::cta;" ::: "memory");

    // threads 0..15 each push one 1KB row to global via bulk async copy
    if (t < 16) {
        int y = y0 + t;
        char* g = (char*)out4 + ((size_t)((((b << 9) + y) << 9) + x0)) * 64;
        uint32_t s = (uint32_t)__cvta_generic_to_shared(&sout[t << 6]);
        asm volatile("cp.async.bulk.global.shared::cta.bulk_group [%0], [%1], %2;\n"
                     :: "l"(g), "r"(s), "r"(1024) : "memory");
        asm volatile("cp.async.bulk.commit_group;\n" ::: "memory");
        asm volatile("cp.async.bulk.wait_group 0;\n" ::: "memory");
    }
}

extern "C" void kernel_launch(void* const* d_in, const int* in_sizes, int n_in,
                              void* d_out, int out_size)
{
    const float4* img4  = (const float4*)d_in[0];
    const float2* flow2 = (const float2*)d_in[1];
    float4* out4 = (float4*)d_out;

    dim3 grid(Ww / 16, Hh / 16, 8);
    warp_kernel_bulk<<<grid, 256>>>(img4, flow2, out4);
}